// round 1
// baseline (speedup 1.0000x reference)
#include <cuda_runtime.h>
#include <math.h>
#include <stdint.h>

// Problem constants
#define BSZ 8192
#define DD  1024
#define NTOT 16384            // 2*BSZ columns of sims
static __constant__ const float kTempInv = 20.0f;   // 1/0.05
#define EPSN 1e-8f

// Scratch: normalized (and tf32-rounded) copies of the three matrices.
__device__ float g_pn[BSZ * DD];
__device__ float g_en[BSZ * DD];
__device__ float g_cn[BSZ * DD];
__device__ float g_rowloss[BSZ];

// ---------------------------------------------------------------------------
// helpers
// ---------------------------------------------------------------------------
__device__ __forceinline__ float tf32_round(float x) {
    uint32_t u;
    asm("cvt.rna.tf32.f32 %0, %1;" : "=r"(u) : "f"(x));
    return __uint_as_float(u);
}

__device__ __forceinline__ void mma_tf32(float* c, const uint32_t* a, const uint32_t* b) {
    asm volatile(
        "mma.sync.aligned.m16n8k8.row.col.f32.tf32.tf32.f32 "
        "{%0,%1,%2,%3}, {%4,%5,%6,%7}, {%8,%9}, {%0,%1,%2,%3};"
        : "+f"(c[0]), "+f"(c[1]), "+f"(c[2]), "+f"(c[3])
        : "r"(a[0]), "r"(a[1]), "r"(a[2]), "r"(a[3]),
          "r"(b[0]), "r"(b[1]));
}

// ---------------------------------------------------------------------------
// Kernel 1: L2-normalize each row (clamping norm at EPSN), round to tf32 grid.
// grid = (BSZ, 3), block = 256. Each block handles one row of one matrix.
// ---------------------------------------------------------------------------
__global__ void normalize_kernel(const float* __restrict__ p,
                                 const float* __restrict__ e,
                                 const float* __restrict__ c) {
    int row   = blockIdx.x;
    int which = blockIdx.y;
    const float* src = (which == 0) ? p : (which == 1) ? e : c;
    float*       dst = (which == 0) ? g_pn : (which == 1) ? g_en : g_cn;

    const float4* s4 = reinterpret_cast<const float4*>(src + (size_t)row * DD);
    float4 v = s4[threadIdx.x];                     // 256 threads * 4 = 1024
    float ss = v.x * v.x + v.y * v.y + v.z * v.z + v.w * v.w;

    // warp reduce
    #pragma unroll
    for (int off = 16; off; off >>= 1)
        ss += __shfl_xor_sync(0xffffffffu, ss, off);

    __shared__ float red[8];
    __shared__ float s_inv;
    int wid  = threadIdx.x >> 5;
    int lane = threadIdx.x & 31;
    if (lane == 0) red[wid] = ss;
    __syncthreads();
    if (threadIdx.x == 0) {
        float tot = 0.f;
        #pragma unroll
        for (int i = 0; i < 8; i++) tot += red[i];
        float n = sqrtf(tot);
        s_inv = 1.0f / fmaxf(n, EPSN);
    }
    __syncthreads();
    float inv = s_inv;

    float4 o;
    o.x = tf32_round(v.x * inv);
    o.y = tf32_round(v.y * inv);
    o.z = tf32_round(v.z * inv);
    o.w = tf32_round(v.w * inv);
    reinterpret_cast<float4*>(dst + (size_t)row * DD)[threadIdx.x] = o;
}

// ---------------------------------------------------------------------------
// Kernel 2: sims = [Pn*EnT, Pn*CnT] * (1/TEMP), written to out+1 (row-major
// [BSZ, NTOT]).  CTA tile 128x128, K-chunk 32, 8 warps in 2x4 grid, each warp
// a 64x32 tile built from m16n8k8 tf32 MMAs.
// ---------------------------------------------------------------------------
#define TM 128
#define TN 128
#define TK 32
#define KSTR (TK + 4)   // padded shared stride (floats)

__global__ __launch_bounds__(256, 2) void gemm_kernel(float* __restrict__ out) {
    __shared__ float As[TM * KSTR];
    __shared__ float Bs[TN * KSTR];

    int tid  = threadIdx.x;
    int wid  = tid >> 5;
    int lane = tid & 31;
    int grp  = lane >> 2;       // groupID (0..7)
    int tig  = lane & 3;        // thread-in-group (0..3)
    int warp_m = wid >> 2;      // 0..1
    int warp_n = wid & 3;       // 0..3

    int ctaM = blockIdx.y * TM;
    int ctaN = blockIdx.x * TN;

    const float* Aptr = g_pn + (size_t)ctaM * DD;
    const float* Bptr = (ctaN < BSZ) ? (g_en + (size_t)ctaN * DD)
                                     : (g_cn + (size_t)(ctaN - BSZ) * DD);

    float acc[4][4][4];
    #pragma unroll
    for (int i = 0; i < 4; i++)
        #pragma unroll
        for (int j = 0; j < 4; j++)
            #pragma unroll
            for (int k = 0; k < 4; k++) acc[i][j][k] = 0.f;

    int ldrow = tid >> 3;        // 0..31
    int ldc   = (tid & 7) * 4;   // 0..28

    for (int k0 = 0; k0 < DD; k0 += TK) {
        #pragma unroll
        for (int i = 0; i < 4; i++) {
            int r = ldrow + 32 * i;
            float4 va = *reinterpret_cast<const float4*>(Aptr + (size_t)r * DD + k0 + ldc);
            *reinterpret_cast<float4*>(&As[r * KSTR + ldc]) = va;
            float4 vb = *reinterpret_cast<const float4*>(Bptr + (size_t)r * DD + k0 + ldc);
            *reinterpret_cast<float4*>(&Bs[r * KSTR + ldc]) = vb;
        }
        __syncthreads();

        #pragma unroll
        for (int kk = 0; kk < TK; kk += 8) {
            uint32_t afr[4][4];
            uint32_t bfr[4][2];
            #pragma unroll
            for (int mt = 0; mt < 4; mt++) {
                int r0 = warp_m * 64 + mt * 16 + grp;
                afr[mt][0] = __float_as_uint(As[r0 * KSTR + kk + tig]);
                afr[mt][1] = __float_as_uint(As[(r0 + 8) * KSTR + kk + tig]);
                afr[mt][2] = __float_as_uint(As[r0 * KSTR + kk + tig + 4]);
                afr[mt][3] = __float_as_uint(As[(r0 + 8) * KSTR + kk + tig + 4]);
            }
            #pragma unroll
            for (int nt = 0; nt < 4; nt++) {
                int c0 = warp_n * 32 + nt * 8 + grp;
                bfr[nt][0] = __float_as_uint(Bs[c0 * KSTR + kk + tig]);
                bfr[nt][1] = __float_as_uint(Bs[c0 * KSTR + kk + tig + 4]);
            }
            #pragma unroll
            for (int mt = 0; mt < 4; mt++)
                #pragma unroll
                for (int nt = 0; nt < 4; nt++)
                    mma_tf32(acc[mt][nt], afr[mt], bfr[nt]);
        }
        __syncthreads();
    }

    // store (scaled by 1/TEMP); sims starts at out+1 (loss occupies out[0])
    float* simout = out + 1;
    #pragma unroll
    for (int mt = 0; mt < 4; mt++) {
        int r = ctaM + warp_m * 64 + mt * 16 + grp;
        #pragma unroll
        for (int nt = 0; nt < 4; nt++) {
            int cc = ctaN + warp_n * 32 + nt * 8 + 2 * tig;
            size_t base0 = (size_t)r * NTOT + cc;
            size_t base1 = (size_t)(r + 8) * NTOT + cc;
            simout[base0]     = acc[mt][nt][0] * kTempInv;
            simout[base0 + 1] = acc[mt][nt][1] * kTempInv;
            simout[base1]     = acc[mt][nt][2] * kTempInv;
            simout[base1 + 1] = acc[mt][nt][3] * kTempInv;
        }
    }
}

// ---------------------------------------------------------------------------
// Kernel 3: per-row logsumexp over NTOT cols + diagonal target.
// grid = BSZ blocks, 256 threads.
// ---------------------------------------------------------------------------
__global__ void lse_kernel(const float* __restrict__ sims) {
    int row = blockIdx.x;
    const float* rp = sims + (size_t)row * NTOT;

    float m = -INFINITY, s = 0.f;
    for (int c = threadIdx.x; c < NTOT; c += 256) {
        float v = rp[c];
        if (v > m) {
            s = s * __expf(m - v) + 1.0f;
            m = v;
        } else {
            s += __expf(v - m);
        }
    }
    // warp-level pair combine
    #pragma unroll
    for (int off = 16; off; off >>= 1) {
        float m2 = __shfl_xor_sync(0xffffffffu, m, off);
        float s2 = __shfl_xor_sync(0xffffffffu, s, off);
        float M = fmaxf(m, m2);
        s = s * __expf(m - M) + s2 * __expf(m2 - M);
        m = M;
    }
    __shared__ float sm[8], ssum[8];
    int wid  = threadIdx.x >> 5;
    int lane = threadIdx.x & 31;
    if (lane == 0) { sm[wid] = m; ssum[wid] = s; }
    __syncthreads();
    if (threadIdx.x == 0) {
        float M = sm[0];
        #pragma unroll
        for (int i = 1; i < 8; i++) M = fmaxf(M, sm[i]);
        float S = 0.f;
        #pragma unroll
        for (int i = 0; i < 8; i++) S += ssum[i] * __expf(sm[i] - M);
        float logz = M + logf(S);
        float tgt  = rp[row];           // diagonal of first half
        g_rowloss[row] = logz - tgt;
    }
}

// ---------------------------------------------------------------------------
// Kernel 4: mean over rows -> loss at out[0].
// ---------------------------------------------------------------------------
__global__ void loss_kernel(float* __restrict__ out) {
    float s = 0.f;
    for (int i = threadIdx.x; i < BSZ; i += 256) s += g_rowloss[i];
    #pragma unroll
    for (int off = 16; off; off >>= 1)
        s += __shfl_xor_sync(0xffffffffu, s, off);
    __shared__ float red[8];
    int wid  = threadIdx.x >> 5;
    int lane = threadIdx.x & 31;
    if (lane == 0) red[wid] = s;
    __syncthreads();
    if (threadIdx.x == 0) {
        float tot = 0.f;
        #pragma unroll
        for (int i = 0; i < 8; i++) tot += red[i];
        out[0] = tot / (float)BSZ;
    }
}

// ---------------------------------------------------------------------------
extern "C" void kernel_launch(void* const* d_in, const int* in_sizes, int n_in,
                              void* d_out, int out_size) {
    const float* p = (const float*)d_in[0];
    const float* e = (const float*)d_in[1];
    const float* c = (const float*)d_in[2];
    float* out = (float*)d_out;

    normalize_kernel<<<dim3(BSZ, 3), 256>>>(p, e, c);
    gemm_kernel<<<dim3(NTOT / TN, BSZ / TM), 256>>>(out);
    lse_kernel<<<BSZ, 256>>>(out + 1);
    loss_kernel<<<1, 256>>>(out);
}

// round 7
// speedup vs baseline: 1.1045x; 1.1045x over previous
#include <cuda_runtime.h>
#include <math.h>
#include <stdint.h>

// ---------------------------------------------------------------------------
// Problem constants
// ---------------------------------------------------------------------------
#define BSZ  8192
#define DD   1024
#define NTOT 16384
#define TEMPI 20.0f
#define EPSN 1e-8f
#define LSE_SHIFT 20.0f       // sims = 20*cos <= 20 strictly

// GEMM tiling
#define TM 128
#define TN 256
#define TK 32                  // K elements per chunk (128 B per row)
#define NSTAGE 3
#define CHUNKS (DD / TK)       // 32
#define NTILES (NTOT / TN)     // 64

#define KSTR 36                                    // padded row stride (floats)
#define A_BYTES_P (TM * KSTR * 4)                  // 18432
#define B_BYTES_P (TN * KSTR * 4)                  // 36864
#define STAGE_BYTES (A_BYTES_P + B_BYTES_P)        // 55296
#define STAGE_FL (STAGE_BYTES / 4)
#define SMEM_TOTAL (NSTAGE * STAGE_BYTES)          // 165888

// ---------------------------------------------------------------------------
// Scratch
// ---------------------------------------------------------------------------
__device__ float g_pn[BSZ * DD];
__device__ float g_en[BSZ * DD];
__device__ float g_cn[BSZ * DD];
__device__ float g_psum[BSZ * NTILES];
__device__ float g_rowloss[BSZ];

// ---------------------------------------------------------------------------
// helpers
// ---------------------------------------------------------------------------
__device__ __forceinline__ uint32_t smem_u32(const void* p) {
    uint32_t a;
    asm("{ .reg .u64 t; cvta.to.shared.u64 t, %1; cvt.u32.u64 %0, t; }" : "=r"(a) : "l"(p));
    return a;
}
__device__ __forceinline__ float tf32_round(float x) {
    uint32_t u;
    asm("cvt.rna.tf32.f32 %0, %1;" : "=r"(u) : "f"(x));
    return __uint_as_float(u);
}
__device__ __forceinline__ void cp_async16(uint32_t dst, const void* src) {
    asm volatile("cp.async.cg.shared.global [%0], [%1], 16;" :: "r"(dst), "l"(src) : "memory");
}
__device__ __forceinline__ void cp_commit() {
    asm volatile("cp.async.commit_group;" ::: "memory");
}
__device__ __forceinline__ void cp_wait2() {
    asm volatile("cp.async.wait_group %0;" :: "n"(NSTAGE - 1) : "memory");
}
__device__ __forceinline__ void mma_tf32(float* c, const uint32_t* a, const uint32_t* b) {
    asm volatile(
        "mma.sync.aligned.m16n8k8.row.col.f32.tf32.tf32.f32 "
        "{%0,%1,%2,%3}, {%4,%5,%6,%7}, {%8,%9}, {%0,%1,%2,%3};"
        : "+f"(c[0]), "+f"(c[1]), "+f"(c[2]), "+f"(c[3])
        : "r"(a[0]), "r"(a[1]), "r"(a[2]), "r"(a[3]),
          "r"(b[0]), "r"(b[1]));
}

// ---------------------------------------------------------------------------
// Kernel 1: L2-normalize rows, round to tf32.  grid=(BSZ,3), block=256
// ---------------------------------------------------------------------------
__global__ void normalize_kernel(const float* __restrict__ p,
                                 const float* __restrict__ e,
                                 const float* __restrict__ c) {
    int row   = blockIdx.x;
    int which = blockIdx.y;
    const float* src = (which == 0) ? p : (which == 1) ? e : c;
    float*       dst = (which == 0) ? g_pn : (which == 1) ? g_en : g_cn;

    float4 v = reinterpret_cast<const float4*>(src + (size_t)row * DD)[threadIdx.x];
    float ss = v.x * v.x + v.y * v.y + v.z * v.z + v.w * v.w;
    #pragma unroll
    for (int off = 16; off; off >>= 1) ss += __shfl_xor_sync(0xffffffffu, ss, off);

    __shared__ float red[8];
    __shared__ float s_inv;
    if ((threadIdx.x & 31) == 0) red[threadIdx.x >> 5] = ss;
    __syncthreads();
    if (threadIdx.x == 0) {
        float tot = 0.f;
        #pragma unroll
        for (int i = 0; i < 8; i++) tot += red[i];
        s_inv = 1.0f / fmaxf(sqrtf(tot), EPSN);
    }
    __syncthreads();
    float inv = s_inv;
    float4 o;
    o.x = tf32_round(v.x * inv); o.y = tf32_round(v.y * inv);
    o.z = tf32_round(v.z * inv); o.w = tf32_round(v.w * inv);
    reinterpret_cast<float4*>(dst + (size_t)row * DD)[threadIdx.x] = o;
}

// ---------------------------------------------------------------------------
// Kernel 2: pipelined tf32 mma.sync GEMM, 128x256 CTA tile, 8 warps (2x4),
// warp tile 64x64, 3-stage cp.async ring, fused scale + partial LSE epilogue.
// ---------------------------------------------------------------------------
__global__ void __launch_bounds__(256, 1) gemm_kernel(float* __restrict__ out) {
    extern __shared__ char smem[];
    float* Sf = reinterpret_cast<float*>(smem);
    uint32_t sb = smem_u32(smem);

    int tid = threadIdx.x;
    int wid = tid >> 5, lane = tid & 31;
    int grp = lane >> 2, tig = lane & 3;
    int wm = wid >> 2;          // 0..1  (M)
    int wn = wid & 3;           // 0..3  (N)

    int bx = blockIdx.x, by = blockIdx.y;
    int ctaM = by * TM, ctaN = bx * TN;

    const float* Abase = g_pn + (size_t)ctaM * DD;
    const float* Bbase = (ctaN < BSZ) ? (g_en + (size_t)ctaN * DD)
                                      : (g_cn + (size_t)(ctaN - BSZ) * DD);

    // per-thread load coordinates (granule = 16B)
    int ar[4], ac[4], br[8], bc[8];
    #pragma unroll
    for (int j = 0; j < 4; j++) { int g = tid + 256 * j; ar[j] = g >> 3; ac[j] = (g & 7) * 4; }
    #pragma unroll
    for (int j = 0; j < 8; j++) { int g = tid + 256 * j; br[j] = g >> 3; bc[j] = (g & 7) * 4; }

    float acc[4][8][4];
    #pragma unroll
    for (int mt = 0; mt < 4; mt++)
        #pragma unroll
        for (int nt = 0; nt < 8; nt++)
            #pragma unroll
            for (int k = 0; k < 4; k++) acc[mt][nt][k] = 0.f;

    // ---- prologue: fill 3 stages ----
    #pragma unroll
    for (int i = 0; i < NSTAGE; i++) {
        uint32_t stage = sb + i * STAGE_BYTES;
        #pragma unroll
        for (int j = 0; j < 4; j++)
            cp_async16(stage + (ar[j] * KSTR + ac[j]) * 4,
                       Abase + (size_t)ar[j] * DD + i * TK + ac[j]);
        #pragma unroll
        for (int j = 0; j < 8; j++)
            cp_async16(stage + A_BYTES_P + (br[j] * KSTR + bc[j]) * 4,
                       Bbase + (size_t)br[j] * DD + i * TK + bc[j]);
        cp_commit();
    }

    // ---- mainloop ----
    #pragma unroll 1
    for (int i = 0; i < CHUNKS; i++) {
        cp_wait2();
        __syncthreads();
        int s = i % NSTAGE;
        const float* As = Sf + s * STAGE_FL;
        const float* Bs = As + TM * KSTR;

        #pragma unroll
        for (int kk = 0; kk < TK; kk += 8) {
            uint32_t afr[4][4], bfr[8][2];
            #pragma unroll
            for (int mt = 0; mt < 4; mt++) {
                int r0 = wm * 64 + mt * 16 + grp;
                afr[mt][0] = __float_as_uint(As[r0 * KSTR + kk + tig]);
                afr[mt][1] = __float_as_uint(As[(r0 + 8) * KSTR + kk + tig]);
                afr[mt][2] = __float_as_uint(As[r0 * KSTR + kk + tig + 4]);
                afr[mt][3] = __float_as_uint(As[(r0 + 8) * KSTR + kk + tig + 4]);
            }
            #pragma unroll
            for (int nt = 0; nt < 8; nt++) {
                int c0 = wn * 64 + nt * 8 + grp;
                bfr[nt][0] = __float_as_uint(Bs[c0 * KSTR + kk + tig]);
                bfr[nt][1] = __float_as_uint(Bs[c0 * KSTR + kk + tig + 4]);
            }
            #pragma unroll
            for (int mt = 0; mt < 4; mt++)
                #pragma unroll
                for (int nt = 0; nt < 8; nt++)
                    mma_tf32(acc[mt][nt], afr[mt], bfr[nt]);
        }
        __syncthreads();

        int nc = i + NSTAGE;
        if (nc < CHUNKS) {
            uint32_t stage = sb + s * STAGE_BYTES;
            #pragma unroll
            for (int j = 0; j < 4; j++)
                cp_async16(stage + (ar[j] * KSTR + ac[j]) * 4,
                           Abase + (size_t)ar[j] * DD + nc * TK + ac[j]);
            #pragma unroll
            for (int j = 0; j < 8; j++)
                cp_async16(stage + A_BYTES_P + (br[j] * KSTR + bc[j]) * 4,
                           Bbase + (size_t)br[j] * DD + nc * TK + bc[j]);
        }
        cp_commit();   // commit every iter (possibly empty) to keep counts uniform
    }

    // ---- epilogue: scale, store sims, fused partial LSE ----
    float* simout = out + 1;
    float* sred = Sf;          // 128 rows x 4 warpn partials (stages are dead now)

    #pragma unroll
    for (int mt = 0; mt < 4; mt++) {
        int rl0 = wm * 64 + mt * 16 + grp;     // local row (0..127)
        int r0 = ctaM + rl0;
        size_t rb0 = (size_t)r0 * NTOT + ctaN + wn * 64;
        size_t rb1 = rb0 + (size_t)8 * NTOT;
        float s0 = 0.f, s1 = 0.f;
        #pragma unroll
        for (int nt = 0; nt < 8; nt++) {
            int cof = nt * 8 + tig * 2;
            float v0 = acc[mt][nt][0] * TEMPI;
            float v1 = acc[mt][nt][1] * TEMPI;
            float v2 = acc[mt][nt][2] * TEMPI;
            float v3 = acc[mt][nt][3] * TEMPI;
            simout[rb0 + cof]     = v0;
            simout[rb0 + cof + 1] = v1;
            simout[rb1 + cof]     = v2;
            simout[rb1 + cof + 1] = v3;
            s0 += __expf(v0 - LSE_SHIFT) + __expf(v1 - LSE_SHIFT);
            s1 += __expf(v2 - LSE_SHIFT) + __expf(v3 - LSE_SHIFT);
        }
        // reduce over tig lanes (quad)
        s0 += __shfl_xor_sync(0xffffffffu, s0, 1);
        s0 += __shfl_xor_sync(0xffffffffu, s0, 2);
        s1 += __shfl_xor_sync(0xffffffffu, s1, 1);
        s1 += __shfl_xor_sync(0xffffffffu, s1, 2);
        if (tig == 0) {
            sred[rl0 * 4 + wn]       = s0;
            sred[(rl0 + 8) * 4 + wn] = s1;
        }
    }
    __syncthreads();
    if (tid < TM) {
        float s = sred[tid * 4] + sred[tid * 4 + 1] + sred[tid * 4 + 2] + sred[tid * 4 + 3];
        g_psum[(size_t)(ctaM + tid) * NTILES + bx] = s;
    }
}

// ---------------------------------------------------------------------------
// Kernel 3: combine NTILES partial sums per row.  grid=BSZ, block=64
// ---------------------------------------------------------------------------
__global__ void lse_final_kernel(const float* __restrict__ sims) {
    int row = blockIdx.x;
    float s = g_psum[(size_t)row * NTILES + threadIdx.x];
    #pragma unroll
    for (int off = 16; off; off >>= 1) s += __shfl_xor_sync(0xffffffffu, s, off);
    __shared__ float red[2];
    if ((threadIdx.x & 31) == 0) red[threadIdx.x >> 5] = s;
    __syncthreads();
    if (threadIdx.x == 0) {
        float S = red[0] + red[1];
        float tgt = sims[(size_t)row * NTOT + row];
        g_rowloss[row] = LSE_SHIFT + logf(S) - tgt;
    }
}

// ---------------------------------------------------------------------------
// Kernel 4: mean over rows -> out[0]
// ---------------------------------------------------------------------------
__global__ void loss_kernel(float* __restrict__ out) {
    float s = 0.f;
    for (int i = threadIdx.x; i < BSZ; i += 256) s += g_rowloss[i];
    #pragma unroll
    for (int off = 16; off; off >>= 1) s += __shfl_xor_sync(0xffffffffu, s, off);
    __shared__ float red[8];
    if ((threadIdx.x & 31) == 0) red[threadIdx.x >> 5] = s;
    __syncthreads();
    if (threadIdx.x == 0) {
        float tot = 0.f;
        #pragma unroll
        for (int i = 0; i < 8; i++) tot += red[i];
        out[0] = tot / (float)BSZ;
    }
}

// ---------------------------------------------------------------------------
extern "C" void kernel_launch(void* const* d_in, const int* in_sizes, int n_in,
                              void* d_out, int out_size) {
    const float* p = (const float*)d_in[0];
    const float* e = (const float*)d_in[1];
    const float* c = (const float*)d_in[2];
    float* out = (float*)d_out;

    cudaFuncSetAttribute(gemm_kernel, cudaFuncAttributeMaxDynamicSharedMemorySize, SMEM_TOTAL);

    normalize_kernel<<<dim3(BSZ, 3), 256>>>(p, e, c);
    gemm_kernel<<<dim3(NTOT / TN, BSZ / TM), 256, SMEM_TOTAL>>>(out);
    lse_final_kernel<<<BSZ, 64>>>(out + 1);
    loss_kernel<<<1, 256>>>(out);
}

// round 9
// speedup vs baseline: 1.1444x; 1.0361x over previous
#include <cuda_runtime.h>
#include <math.h>
#include <stdint.h>

// ---------------------------------------------------------------------------
// Problem constants
// ---------------------------------------------------------------------------
#define BSZ  8192
#define DD   1024
#define NTOT 16384
#define TEMPI 20.0f
#define EPSN 1e-8f
#define LSE_SHIFT 20.0f       // sims = 20*cos <= 20 strictly

// GEMM tiling
#define TM 128
#define TN 256
#define TK 32                  // K floats per chunk
#define NSTAGE 3
#define CHUNKS (DD / TK)       // 32
#define NTILES (NTOT / TN)     // 64

#define KSTR 40                                    // padded row stride (floats)
#define A_BYTES_P (TM * KSTR * 4)                  // 20480
#define B_BYTES_P (TN * KSTR * 4)                  // 40960
#define STAGE_BYTES (A_BYTES_P + B_BYTES_P)        // 61440
#define STAGE_FL (STAGE_BYTES / 4)
#define SMEM_TOTAL (NSTAGE * STAGE_BYTES)          // 184320

// ---------------------------------------------------------------------------
// Scratch (stored K-INTERLEAVED: within each 8-float group of a row,
// value with local index j sits at position 2*(j&3) + (j>>2))
// ---------------------------------------------------------------------------
__device__ float g_pn[BSZ * DD];
__device__ float g_en[BSZ * DD];
__device__ float g_cn[BSZ * DD];
__device__ float g_psum[BSZ * NTILES];
__device__ float g_rowloss[BSZ];

// ---------------------------------------------------------------------------
// helpers
// ---------------------------------------------------------------------------
__device__ __forceinline__ uint32_t smem_u32(const void* p) {
    uint32_t a;
    asm("{ .reg .u64 t; cvta.to.shared.u64 t, %1; cvt.u32.u64 %0, t; }" : "=r"(a) : "l"(p));
    return a;
}
__device__ __forceinline__ float tf32_round(float x) {
    uint32_t u;
    asm("cvt.rna.tf32.f32 %0, %1;" : "=r"(u) : "f"(x));
    return __uint_as_float(u);
}
__device__ __forceinline__ void cp_async16(uint32_t dst, const void* src) {
    asm volatile("cp.async.cg.shared.global [%0], [%1], 16;" :: "r"(dst), "l"(src) : "memory");
}
__device__ __forceinline__ void cp_commit() {
    asm volatile("cp.async.commit_group;" ::: "memory");
}
__device__ __forceinline__ void cp_wait_1() {
    asm volatile("cp.async.wait_group 1;" ::: "memory");
}
__device__ __forceinline__ void mma_tf32(float* c,
                                         uint32_t a0, uint32_t a1, uint32_t a2, uint32_t a3,
                                         uint32_t b0, uint32_t b1) {
    asm volatile(
        "mma.sync.aligned.m16n8k8.row.col.f32.tf32.tf32.f32 "
        "{%0,%1,%2,%3}, {%4,%5,%6,%7}, {%8,%9}, {%0,%1,%2,%3};"
        : "+f"(c[0]), "+f"(c[1]), "+f"(c[2]), "+f"(c[3])
        : "r"(a0), "r"(a1), "r"(a2), "r"(a3), "r"(b0), "r"(b1));
}

// ---------------------------------------------------------------------------
// Kernel 1: L2-normalize rows, round to tf32, store K-interleaved.
// grid=(BSZ,3), block=256
// ---------------------------------------------------------------------------
__global__ void normalize_kernel(const float* __restrict__ p,
                                 const float* __restrict__ e,
                                 const float* __restrict__ c) {
    int row   = blockIdx.x;
    int which = blockIdx.y;
    const float* src = (which == 0) ? p : (which == 1) ? e : c;
    float*       dst = (which == 0) ? g_pn : (which == 1) ? g_en : g_cn;

    float4 v = reinterpret_cast<const float4*>(src + (size_t)row * DD)[threadIdx.x];
    float ss = v.x * v.x + v.y * v.y + v.z * v.z + v.w * v.w;
    #pragma unroll
    for (int off = 16; off; off >>= 1) ss += __shfl_xor_sync(0xffffffffu, ss, off);

    __shared__ float red[8];
    __shared__ float s_inv;
    if ((threadIdx.x & 31) == 0) red[threadIdx.x >> 5] = ss;
    __syncthreads();
    if (threadIdx.x == 0) {
        float tot = 0.f;
        #pragma unroll
        for (int i = 0; i < 8; i++) tot += red[i];
        s_inv = 1.0f / fmaxf(sqrtf(tot), EPSN);
    }
    __syncthreads();
    float inv = s_inv;

    // k = 4*t + m  ->  pos = 8*(t>>1) + 2*m + (t&1)
    int t = threadIdx.x;
    float* rp = dst + (size_t)row * DD + 8 * (t >> 1) + (t & 1);
    rp[0] = tf32_round(v.x * inv);
    rp[2] = tf32_round(v.y * inv);
    rp[4] = tf32_round(v.z * inv);
    rp[6] = tf32_round(v.w * inv);
}

// ---------------------------------------------------------------------------
// Kernel 2: pipelined tf32 mma.sync GEMM, 128x256 tile, 8 warps (2x4),
// warp tile 64x64, 3-stage cp.async ring, LDS.64 frag loads (interleaved K),
// register double-buffered fragments, fused scale + partial-LSE epilogue.
// ---------------------------------------------------------------------------
__global__ void __launch_bounds__(256, 1) gemm_kernel(float* __restrict__ out) {
    extern __shared__ char smem[];
    float* Sf = reinterpret_cast<float*>(smem);
    uint32_t sb = smem_u32(smem);

    int tid = threadIdx.x;
    int wid = tid >> 5, lane = tid & 31;
    int grp = lane >> 2, tig = lane & 3;
    int wm = wid >> 2;          // 0..1  (M)
    int wn = wid & 3;           // 0..3  (N)

    int bx = blockIdx.x, by = blockIdx.y;
    int ctaM = by * TM, ctaN = bx * TN;

    const float* Abase = g_pn + (size_t)ctaM * DD;
    const float* Bbase = (ctaN < BSZ) ? (g_en + (size_t)ctaN * DD)
                                      : (g_cn + (size_t)(ctaN - BSZ) * DD);

    float acc[4][8][4];
    #pragma unroll
    for (int mt = 0; mt < 4; mt++)
        #pragma unroll
        for (int nt = 0; nt < 8; nt++)
            #pragma unroll
            for (int k = 0; k < 4; k++) acc[mt][nt][k] = 0.f;

    // per-thread cp.async coordinates (granule = 16 B = 4 floats)
    int arr = tid >> 3, acl = (tid & 7) * 4;          // A: 4 granule rounds
    // (B uses same pattern with 8 rounds)

    // chunk loader: chunk nc -> stage s
    auto load_chunk = [&](int nc, int s) {
        uint32_t stage = sb + s * STAGE_BYTES;
        #pragma unroll
        for (int j = 0; j < 4; j++) {
            int r = arr + 32 * j;
            cp_async16(stage + (uint32_t)(r * (KSTR * 4) + acl * 4),
                       Abase + (size_t)r * DD + nc * TK + acl);
        }
        #pragma unroll
        for (int j = 0; j < 8; j++) {
            int r = arr + 32 * j;
            cp_async16(stage + A_BYTES_P + (uint32_t)(r * (KSTR * 4) + acl * 4),
                       Bbase + (size_t)r * DD + nc * TK + acl);
        }
    };

    // ---- prologue: NSTAGE-1 = 2 stages ----
    load_chunk(0, 0); cp_commit();
    load_chunk(1, 1); cp_commit();

    float2 fa[2][4][2];   // [buf][mt][row half]
    float2 fb[2][8];      // [buf][nt]

    int a_off = (wm * 64 + grp) * KSTR + 2 * tig;
    int b_off = (wn * 64 + grp) * KSTR + 2 * tig;

    // ---- mainloop ----
    #pragma unroll 1
    for (int i = 0; i < CHUNKS; i++) {
        cp_wait_1();
        __syncthreads();
        int s = i % NSTAGE;
        const float* As = Sf + s * STAGE_FL;
        const float* Bs = As + TM * KSTR;

        // prefetch chunk i+2 into the stage consumed last iteration
        if (i + 2 < CHUNKS) load_chunk(i + 2, (i + 2) % NSTAGE);
        cp_commit();

        // load kk-block 0 fragments into buf 0
        #pragma unroll
        for (int mt = 0; mt < 4; mt++) {
            fa[0][mt][0] = *(const float2*)(As + a_off + mt * 16 * KSTR);
            fa[0][mt][1] = *(const float2*)(As + a_off + (mt * 16 + 8) * KSTR);
        }
        #pragma unroll
        for (int nt = 0; nt < 8; nt++)
            fb[0][nt] = *(const float2*)(Bs + b_off + nt * 8 * KSTR);

        #pragma unroll
        for (int kb = 0; kb < 4; kb++) {
            int cur = kb & 1, nxt = cur ^ 1;
            if (kb < 3) {
                int ko = (kb + 1) * 8;
                #pragma unroll
                for (int mt = 0; mt < 4; mt++) {
                    fa[nxt][mt][0] = *(const float2*)(As + a_off + mt * 16 * KSTR + ko);
                    fa[nxt][mt][1] = *(const float2*)(As + a_off + (mt * 16 + 8) * KSTR + ko);
                }
                #pragma unroll
                for (int nt = 0; nt < 8; nt++)
                    fb[nxt][nt] = *(const float2*)(Bs + b_off + nt * 8 * KSTR + ko);
            }
            #pragma unroll
            for (int mt = 0; mt < 4; mt++)
                #pragma unroll
                for (int nt = 0; nt < 8; nt++)
                    mma_tf32(acc[mt][nt],
                             __float_as_uint(fa[cur][mt][0].x),
                             __float_as_uint(fa[cur][mt][1].x),
                             __float_as_uint(fa[cur][mt][0].y),
                             __float_as_uint(fa[cur][mt][1].y),
                             __float_as_uint(fb[cur][nt].x),
                             __float_as_uint(fb[cur][nt].y));
        }
    }
    __syncthreads();   // stages dead; smem reused below

    // ---- epilogue: scale, store sims, fused partial LSE ----
    float* simout = out + 1;
    float* sred = Sf;   // 128 rows x 4 warpn partials

    #pragma unroll
    for (int mt = 0; mt < 4; mt++) {
        int rl0 = wm * 64 + mt * 16 + grp;     // local row (0..127)
        int r0 = ctaM + rl0;
        size_t rb0 = (size_t)r0 * NTOT + ctaN + wn * 64;
        size_t rb1 = rb0 + (size_t)8 * NTOT;
        float s0 = 0.f, s1 = 0.f;
        #pragma unroll
        for (int nt = 0; nt < 8; nt++) {
            int cof = nt * 8 + tig * 2;
            float v0 = acc[mt][nt][0] * TEMPI;
            float v1 = acc[mt][nt][1] * TEMPI;
            float v2 = acc[mt][nt][2] * TEMPI;
            float v3 = acc[mt][nt][3] * TEMPI;
            simout[rb0 + cof]     = v0;
            simout[rb0 + cof + 1] = v1;
            simout[rb1 + cof]     = v2;
            simout[rb1 + cof + 1] = v3;
            s0 += __expf(v0 - LSE_SHIFT) + __expf(v1 - LSE_SHIFT);
            s1 += __expf(v2 - LSE_SHIFT) + __expf(v3 - LSE_SHIFT);
        }
        s0 += __shfl_xor_sync(0xffffffffu, s0, 1);
        s0 += __shfl_xor_sync(0xffffffffu, s0, 2);
        s1 += __shfl_xor_sync(0xffffffffu, s1, 1);
        s1 += __shfl_xor_sync(0xffffffffu, s1, 2);
        if (tig == 0) {
            sred[rl0 * 4 + wn]       = s0;
            sred[(rl0 + 8) * 4 + wn] = s1;
        }
    }
    __syncthreads();
    if (tid < TM) {
        float s = sred[tid * 4] + sred[tid * 4 + 1] + sred[tid * 4 + 2] + sred[tid * 4 + 3];
        g_psum[(size_t)(ctaM + tid) * NTILES + bx] = s;
    }
}

// ---------------------------------------------------------------------------
// Kernel 3: combine NTILES partial sums per row.  grid=BSZ, block=64
// ---------------------------------------------------------------------------
__global__ void lse_final_kernel(const float* __restrict__ sims) {
    int row = blockIdx.x;
    float s = g_psum[(size_t)row * NTILES + threadIdx.x];
    #pragma unroll
    for (int off = 16; off; off >>= 1) s += __shfl_xor_sync(0xffffffffu, s, off);
    __shared__ float red[2];
    if ((threadIdx.x & 31) == 0) red[threadIdx.x >> 5] = s;
    __syncthreads();
    if (threadIdx.x == 0) {
        float S = red[0] + red[1];
        float tgt = sims[(size_t)row * NTOT + row];
        g_rowloss[row] = LSE_SHIFT + logf(S) - tgt;
    }
}

// ---------------------------------------------------------------------------
// Kernel 4: mean over rows -> out[0]
// ---------------------------------------------------------------------------
__global__ void loss_kernel(float* __restrict__ out) {
    float s = 0.f;
    for (int i = threadIdx.x; i < BSZ; i += 256) s += g_rowloss[i];
    #pragma unroll
    for (int off = 16; off; off >>= 1) s += __shfl_xor_sync(0xffffffffu, s, off);
    __shared__ float red[8];
    if ((threadIdx.x & 31) == 0) red[threadIdx.x >> 5] = s;
    __syncthreads();
    if (threadIdx.x == 0) {
        float tot = 0.f;
        #pragma unroll
        for (int i = 0; i < 8; i++) tot += red[i];
        out[0] = tot / (float)BSZ;
    }
}

// ---------------------------------------------------------------------------
extern "C" void kernel_launch(void* const* d_in, const int* in_sizes, int n_in,
                              void* d_out, int out_size) {
    const float* p = (const float*)d_in[0];
    const float* e = (const float*)d_in[1];
    const float* c = (const float*)d_in[2];
    float* out = (float*)d_out;

    cudaFuncSetAttribute(gemm_kernel, cudaFuncAttributeMaxDynamicSharedMemorySize, SMEM_TOTAL);

    normalize_kernel<<<dim3(BSZ, 3), 256>>>(p, e, c);
    gemm_kernel<<<dim3(NTOT / TN, BSZ / TM), 256, SMEM_TOTAL>>>(out);
    lse_final_kernel<<<BSZ, 64>>>(out + 1);
    loss_kernel<<<1, 256>>>(out);
}

// round 11
// speedup vs baseline: 2.1041x; 1.8386x over previous
#include <cuda_runtime.h>
#include <cuda_fp16.h>
#include <math.h>
#include <stdint.h>

// ---------------------------------------------------------------------------
// Problem constants
// ---------------------------------------------------------------------------
#define BSZ  8192
#define DD   1024
#define NTOT 16384
#define TEMPI 20.0f
#define EPSN 1e-8f
#define LSE_SHIFT 20.0f       // sims = 20*cos <= 20 strictly

// GEMM tiling (fp16 m16n8k16)
#define TM 128
#define TN 256
#define TK 64                  // K halves per chunk = 128 B per row
#define NSTAGE 3
#define CHUNKS (DD / TK)       // 16
#define NTILES (NTOT / TN)     // 64

#define A_BYTES (TM * 128)                 // 16384
#define B_BYTES (TN * 128)                 // 32768
#define STAGE_BYTES (A_BYTES + B_BYTES)    // 49152
#define SMEM_TOTAL (NSTAGE * STAGE_BYTES)  // 147456

// ---------------------------------------------------------------------------
// Scratch: fp16, PAIR-INTERLEAVED within each 8-pair (16-elem) group:
// pair j (= k>>1) sits at slot 2*(j&3) + ((j&7)>>2) of its group.
// ---------------------------------------------------------------------------
__device__ __half g_pn[BSZ * DD];
__device__ __half g_en[BSZ * DD];
__device__ __half g_cn[BSZ * DD];
__device__ float  g_psum[BSZ * NTILES];
__device__ float  g_rowloss[BSZ];

// ---------------------------------------------------------------------------
// helpers
// ---------------------------------------------------------------------------
__device__ __forceinline__ uint32_t smem_u32(const void* p) {
    uint32_t a;
    asm("{ .reg .u64 t; cvta.to.shared.u64 t, %1; cvt.u32.u64 %0, t; }" : "=r"(a) : "l"(p));
    return a;
}
__device__ __forceinline__ void cp_async16(uint32_t dst, const void* src) {
    asm volatile("cp.async.cg.shared.global [%0], [%1], 16;" :: "r"(dst), "l"(src) : "memory");
}
__device__ __forceinline__ void cp_commit() {
    asm volatile("cp.async.commit_group;" ::: "memory");
}
__device__ __forceinline__ void cp_wait_1() {
    asm volatile("cp.async.wait_group 1;" ::: "memory");
}
__device__ __forceinline__ void mma_f16(float* c,
                                        uint32_t a0, uint32_t a1, uint32_t a2, uint32_t a3,
                                        uint32_t b0, uint32_t b1) {
    asm volatile(
        "mma.sync.aligned.m16n8k16.row.col.f32.f16.f16.f32 "
        "{%0,%1,%2,%3}, {%4,%5,%6,%7}, {%8,%9}, {%0,%1,%2,%3};"
        : "+f"(c[0]), "+f"(c[1]), "+f"(c[2]), "+f"(c[3])
        : "r"(a0), "r"(a1), "r"(a2), "r"(a3), "r"(b0), "r"(b1));
}

// ---------------------------------------------------------------------------
// Kernel 1: L2-normalize rows, convert to fp16, store pair-interleaved.
// grid=(BSZ,3), block=256
// ---------------------------------------------------------------------------
__global__ void normalize_kernel(const float* __restrict__ p,
                                 const float* __restrict__ e,
                                 const float* __restrict__ c) {
    int row   = blockIdx.x;
    int which = blockIdx.y;
    const float* src = (which == 0) ? p : (which == 1) ? e : c;
    __half*      dst = (which == 0) ? g_pn : (which == 1) ? g_en : g_cn;

    float4 v = reinterpret_cast<const float4*>(src + (size_t)row * DD)[threadIdx.x];
    float ss = v.x * v.x + v.y * v.y + v.z * v.z + v.w * v.w;
    #pragma unroll
    for (int off = 16; off; off >>= 1) ss += __shfl_xor_sync(0xffffffffu, ss, off);

    __shared__ float red[8];
    __shared__ float s_inv;
    if ((threadIdx.x & 31) == 0) red[threadIdx.x >> 5] = ss;
    __syncthreads();
    if (threadIdx.x == 0) {
        float tot = 0.f;
        #pragma unroll
        for (int i = 0; i < 8; i++) tot += red[i];
        s_inv = 1.0f / fmaxf(sqrtf(tot), EPSN);
    }
    __syncthreads();
    float inv = s_inv;

    __half2* drow = reinterpret_cast<__half2*>(dst + (size_t)row * DD);
    int t = threadIdx.x;
    // pairs j0 = 2t (elems v.x,v.y) and j1 = 2t+1 (elems v.z,v.w)
    #pragma unroll
    for (int q = 0; q < 2; q++) {
        int j  = 2 * t + q;
        int g  = j >> 3, jj = j & 7;
        int slot = 2 * (jj & 3) + (jj >> 2);
        float lo = q ? v.z : v.x;
        float hi = q ? v.w : v.y;
        drow[g * 8 + slot] = __floats2half2_rn(lo * inv, hi * inv);
    }
}

// ---------------------------------------------------------------------------
// Kernel 2: pipelined fp16 m16n8k16 GEMM, 128x256 tile, 8 warps (2x4),
// warp tile 64x64, 3-stage cp.async ring, XOR-sector swizzle, LDS.64 frags,
// register double-buffering, fused scale + partial-LSE epilogue.
// ---------------------------------------------------------------------------
__global__ void __launch_bounds__(256, 1) gemm_kernel(float* __restrict__ out) {
    extern __shared__ char smem[];
    char* Sc = smem;
    uint32_t sb = smem_u32(smem);

    int tid = threadIdx.x;
    int wid = tid >> 5, lane = tid & 31;
    int grp = lane >> 2, tig = lane & 3;
    int wm = wid >> 2;          // 0..1  (M)
    int wn = wid & 3;           // 0..3  (N)

    int bx = blockIdx.x, by = blockIdx.y;
    int ctaM = by * TM, ctaN = bx * TN;

    const __half* Abase = g_pn + (size_t)ctaM * DD;
    const __half* Bbase = (ctaN < BSZ) ? (g_en + (size_t)ctaN * DD)
                                       : (g_cn + (size_t)(ctaN - BSZ) * DD);

    float acc[4][8][4];
    #pragma unroll
    for (int mt = 0; mt < 4; mt++)
        #pragma unroll
        for (int nt = 0; nt < 8; nt++)
            #pragma unroll
            for (int k = 0; k < 4; k++) acc[mt][nt][k] = 0.f;

    // cp.async coordinates: 128 B per row-chunk, 8 granules of 16 B
    int lrow = tid >> 3;                 // 0..31
    int c16  = tid & 7;                  // granule within row
    // XOR-swizzled dst byte offset within tile for (row, granule)
    auto dsw = [&](int r) -> uint32_t {
        return (uint32_t)((r * 128 + c16 * 16) ^ ((r & 3) << 5));
    };

    auto load_chunk = [&](int nc, int s) {
        uint32_t stage = sb + s * STAGE_BYTES;
        const __half* Ab = Abase + nc * TK;
        const __half* Bb = Bbase + nc * TK;
        #pragma unroll
        for (int j = 0; j < 4; j++) {
            int r = lrow + 32 * j;
            cp_async16(stage + dsw(r), Ab + (size_t)r * DD + c16 * 8);
        }
        #pragma unroll
        for (int j = 0; j < 8; j++) {
            int r = lrow + 32 * j;
            cp_async16(stage + A_BYTES + dsw(r), Bb + (size_t)r * DD + c16 * 8);
        }
    };

    // ---- prologue ----
    load_chunk(0, 0); cp_commit();
    load_chunk(1, 1); cp_commit();

    // fragment double buffers
    uint2 fa[2][4][2];   // [buf][mt][row half] -> (a0,a2) / (a1,a3)
    uint2 fb[2][8];      // [buf][nt] -> (b0,b1)

    // per-thread read offsets (XOR term constant: row&3 == grp&3)
    uint32_t axor = (uint32_t)((grp & 3) << 5);
    // A row rl byte base = rl*128 ; within-row step offset = s*32 + tig*8 (XOR axor)
    int a_row0 = wm * 64 + grp;
    int b_row0 = wn * 64 + grp;

    // ---- mainloop ----
    #pragma unroll 1
    for (int i = 0; i < CHUNKS; i++) {
        cp_wait_1();
        __syncthreads();
        int s = i % NSTAGE;
        const char* As = Sc + s * STAGE_BYTES;
        const char* Bs = As + A_BYTES;

        if (i + 2 < CHUNKS) load_chunk(i + 2, (i + 2) % NSTAGE);
        cp_commit();

        // load step-0 fragments into buf 0
        {
            uint32_t wo = (0 * 32) ^ axor;
            #pragma unroll
            for (int mt = 0; mt < 4; mt++) {
                int r = a_row0 + mt * 16;
                fa[0][mt][0] = *(const uint2*)(As + r * 128 + wo + tig * 8);
                fa[0][mt][1] = *(const uint2*)(As + (r + 8) * 128 + wo + tig * 8);
            }
            #pragma unroll
            for (int nt = 0; nt < 8; nt++) {
                int r = b_row0 + nt * 8;
                fb[0][nt] = *(const uint2*)(Bs + r * 128 + wo + tig * 8);
            }
        }

        #pragma unroll
        for (int kb = 0; kb < 4; kb++) {
            int cur = kb & 1, nxt = cur ^ 1;
            if (kb < 3) {
                uint32_t wo = (uint32_t)((kb + 1) * 32) ^ axor;
                #pragma unroll
                for (int mt = 0; mt < 4; mt++) {
                    int r = a_row0 + mt * 16;
                    fa[nxt][mt][0] = *(const uint2*)(As + r * 128 + wo + tig * 8);
                    fa[nxt][mt][1] = *(const uint2*)(As + (r + 8) * 128 + wo + tig * 8);
                }
                #pragma unroll
                for (int nt = 0; nt < 8; nt++) {
                    int r = b_row0 + nt * 8;
                    fb[nxt][nt] = *(const uint2*)(Bs + r * 128 + wo + tig * 8);
                }
            }
            #pragma unroll
            for (int mt = 0; mt < 4; mt++)
                #pragma unroll
                for (int nt = 0; nt < 8; nt++)
                    mma_f16(acc[mt][nt],
                            fa[cur][mt][0].x, fa[cur][mt][1].x,
                            fa[cur][mt][0].y, fa[cur][mt][1].y,
                            fb[cur][nt].x, fb[cur][nt].y);
        }
    }
    __syncthreads();   // stages dead; smem reused below

    // ---- epilogue: scale, store sims, fused partial LSE ----
    float* simout = out + 1;
    float* sred = reinterpret_cast<float*>(smem);   // 128 rows x 4 warpn partials

    #pragma unroll
    for (int mt = 0; mt < 4; mt++) {
        int rl0 = wm * 64 + mt * 16 + grp;     // local row (0..127)
        int r0 = ctaM + rl0;
        size_t rb0 = (size_t)r0 * NTOT + ctaN + wn * 64;
        size_t rb1 = rb0 + (size_t)8 * NTOT;
        float s0 = 0.f, s1 = 0.f;
        #pragma unroll
        for (int nt = 0; nt < 8; nt++) {
            int cof = nt * 8 + tig * 2;
            float v0 = acc[mt][nt][0] * TEMPI;
            float v1 = acc[mt][nt][1] * TEMPI;
            float v2 = acc[mt][nt][2] * TEMPI;
            float v3 = acc[mt][nt][3] * TEMPI;
            simout[rb0 + cof]     = v0;
            simout[rb0 + cof + 1] = v1;
            simout[rb1 + cof]     = v2;
            simout[rb1 + cof + 1] = v3;
            s0 += __expf(v0 - LSE_SHIFT) + __expf(v1 - LSE_SHIFT);
            s1 += __expf(v2 - LSE_SHIFT) + __expf(v3 - LSE_SHIFT);
        }
        s0 += __shfl_xor_sync(0xffffffffu, s0, 1);
        s0 += __shfl_xor_sync(0xffffffffu, s0, 2);
        s1 += __shfl_xor_sync(0xffffffffu, s1, 1);
        s1 += __shfl_xor_sync(0xffffffffu, s1, 2);
        if (tig == 0) {
            sred[rl0 * 4 + wn]       = s0;
            sred[(rl0 + 8) * 4 + wn] = s1;
        }
    }
    __syncthreads();
    if (tid < TM) {
        float s = sred[tid * 4] + sred[tid * 4 + 1] + sred[tid * 4 + 2] + sred[tid * 4 + 3];
        g_psum[(size_t)(ctaM + tid) * NTILES + bx] = s;
    }
}

// ---------------------------------------------------------------------------
// Kernel 3: combine NTILES partial sums per row.  grid=BSZ, block=64
// ---------------------------------------------------------------------------
__global__ void lse_final_kernel(const float* __restrict__ sims) {
    int row = blockIdx.x;
    float s = g_psum[(size_t)row * NTILES + threadIdx.x];
    #pragma unroll
    for (int off = 16; off; off >>= 1) s += __shfl_xor_sync(0xffffffffu, s, off);
    __shared__ float red[2];
    if ((threadIdx.x & 31) == 0) red[threadIdx.x >> 5] = s;
    __syncthreads();
    if (threadIdx.x == 0) {
        float S = red[0] + red[1];
        float tgt = sims[(size_t)row * NTOT + row];
        g_rowloss[row] = LSE_SHIFT + logf(S) - tgt;
    }
}

// ---------------------------------------------------------------------------
// Kernel 4: mean over rows -> out[0]
// ---------------------------------------------------------------------------
__global__ void loss_kernel(float* __restrict__ out) {
    float s = 0.f;
    for (int i = threadIdx.x; i < BSZ; i += 256) s += g_rowloss[i];
    #pragma unroll
    for (int off = 16; off; off >>= 1) s += __shfl_xor_sync(0xffffffffu, s, off);
    __shared__ float red[8];
    if ((threadIdx.x & 31) == 0) red[threadIdx.x >> 5] = s;
    __syncthreads();
    if (threadIdx.x == 0) {
        float tot = 0.f;
        #pragma unroll
        for (int i = 0; i < 8; i++) tot += red[i];
        out[0] = tot / (float)BSZ;
    }
}

// ---------------------------------------------------------------------------
extern "C" void kernel_launch(void* const* d_in, const int* in_sizes, int n_in,
                              void* d_out, int out_size) {
    const float* p = (const float*)d_in[0];
    const float* e = (const float*)d_in[1];
    const float* c = (const float*)d_in[2];
    float* out = (float*)d_out;

    cudaFuncSetAttribute(gemm_kernel, cudaFuncAttributeMaxDynamicSharedMemorySize, SMEM_TOTAL);

    normalize_kernel<<<dim3(BSZ, 3), 256>>>(p, e, c);
    gemm_kernel<<<dim3(NTOT / TN, BSZ / TM), 256, SMEM_TOTAL>>>(out);
    lse_final_kernel<<<BSZ, 64>>>(out + 1);
    loss_kernel<<<1, 256>>>(out);
}